// round 16
// baseline (speedup 1.0000x reference)
#include <cuda_runtime.h>
#include <cuda_bf16.h>
#include <cstdint>

#define CCH 64          // C_in == C_out == 64
#define MT  128         // pairs (M rows) per tile
#define APITCH 72       // bf16 elems per smem row (144 B) -> ldmatrix conflict-free
#define BN_EPS 1e-5f

// smem byte offsets (dynamic smem, 1024-aligned base)
#define OFF_AHI 0
#define OFF_ALO (MT * APITCH * 2)                 // 18432
#define OFF_BHI (2 * MT * APITCH * 2)             // 36864
#define OFF_BLO (OFF_BHI + CCH * APITCH * 2)      // 46080
#define SMEM_BYTES (OFF_BLO + CCH * APITCH * 2)   // 55296 -> 2 CTAs/SM

__device__ float g_stats[2 * CCH];   // [0..63]=sum, [64..127]=sum of squares

// ======================= PTX helpers =======================
static __device__ __forceinline__ uint32_t smem_u32(const void* p) {
    uint32_t a;
    asm("{ .reg .u64 t; cvta.to.shared.u64 t, %1; cvt.u32.u64 %0, t; }" : "=r"(a) : "l"(p));
    return a;
}
static __device__ __forceinline__ void ldsm_x4(uint32_t& r0, uint32_t& r1,
                                               uint32_t& r2, uint32_t& r3, uint32_t addr) {
    asm volatile("ldmatrix.sync.aligned.m8n8.x4.shared.b16 {%0,%1,%2,%3}, [%4];"
                 : "=r"(r0), "=r"(r1), "=r"(r2), "=r"(r3) : "r"(addr));
}
static __device__ __forceinline__ void ldsm_x4_t(uint32_t& r0, uint32_t& r1,
                                                 uint32_t& r2, uint32_t& r3, uint32_t addr) {
    asm volatile("ldmatrix.sync.aligned.m8n8.x4.trans.shared.b16 {%0,%1,%2,%3}, [%4];"
                 : "=r"(r0), "=r"(r1), "=r"(r2), "=r"(r3) : "r"(addr));
}
static __device__ __forceinline__ void mma_bf16(float* c, const uint32_t* a,
                                                uint32_t b0, uint32_t b1) {
    asm volatile(
        "mma.sync.aligned.m16n8k16.row.col.f32.bf16.bf16.f32 "
        "{%0,%1,%2,%3}, {%4,%5,%6,%7}, {%8,%9}, {%0,%1,%2,%3};"
        : "+f"(c[0]), "+f"(c[1]), "+f"(c[2]), "+f"(c[3])
        : "r"(a[0]), "r"(a[1]), "r"(a[2]), "r"(a[3]), "r"(b0), "r"(b1));
}
static __device__ __forceinline__ void red4(float* p, float a, float b, float c, float d) {
    asm volatile("red.global.add.v4.f32 [%0], {%1,%2,%3,%4};"
                 :: "l"(p), "f"(a), "f"(b), "f"(c), "f"(d) : "memory");
}
static __device__ __forceinline__ void sts2(uint32_t addr, uint32_t a, uint32_t b) {
    asm volatile("st.shared.v2.b32 [%0], {%1,%2};" :: "r"(addr), "r"(a), "r"(b));
}
// split f32 pair -> bf16x2 hi + bf16x2 lo (packed u32 each)
static __device__ __forceinline__ void split2(float x, float y, uint32_t& hi, uint32_t& lo) {
    __nv_bfloat162 h = __float22bfloat162_rn(make_float2(x, y));
    float2 hf = __bfloat1622float2(h);
    __nv_bfloat162 l = __float22bfloat162_rn(make_float2(x - hf.x, y - hf.y));
    hi = *reinterpret_cast<uint32_t*>(&h);
    lo = *reinterpret_cast<uint32_t*>(&l);
}

// ===========================================================================
// Persistent: gather -> 128x64x64 bf16-split MMA -> shuffle -> red.v4 scatter
// ===========================================================================
__global__ void __launch_bounds__(256, 2)
k_scatter(const float* __restrict__ feat, const float* __restrict__ W,
          const int* __restrict__ pin, const int* __restrict__ pout,
          float* __restrict__ out, int P, int tilesPerK, int tilesTotal)
{
    extern __shared__ __align__(1024) char smem[];
    const uint32_t sb = smem_u32(smem);

    const int tid  = threadIdx.x;
    const int warp = tid >> 5;
    const int lane = tid & 31;

    // static contiguous tile range per CTA (k-major: k changes rarely)
    const int t0 = (int)((long long)blockIdx.x * tilesTotal / gridDim.x);
    const int t1 = (int)((long long)(blockIdx.x + 1) * tilesTotal / gridDim.x);

    // lane-invariant parts of ldmatrix addresses
    const int warpM = warp * 16;
    const int lrow  = lane & 15;
    const int lhalf = (lane >> 4) * 8;
    const uint32_t aLaneOff = (uint32_t)((warpM + lrow) * APITCH + lhalf) * 2;
    const uint32_t bLaneOff = (uint32_t)(lrow * APITCH + lhalf) * 2;
    const int groupID = lane >> 2;
    const int tig     = lane & 3;

    int curK = -1;
    for (int t = t0; t < t1; ++t) {
        const int k  = t / tilesPerK;
        const int pb = t - k * tilesPerK;
        const int base = pb * MT;
        const int* pin_k  = pin  + (size_t)k * P;
        const int* pout_k = pout + (size_t)k * P;

        // ---- (rare) weight tile: W[k]=[ci][co] row-major = B[k=ci][n=co]; hi/lo ----
        if (k != curK) {
            curK = k;
            const float4* Wv = (const float4*)(W + (size_t)k * CCH * CCH);
            #pragma unroll
            for (int q = tid; q < CCH * CCH / 4; q += 256) {
                const int kk = q >> 4, n4 = (q & 15) * 4;
                float4 v = __ldg(Wv + q);
                uint32_t h01, l01, h23, l23;
                split2(v.x, v.y, h01, l01);
                split2(v.z, v.w, h23, l23);
                const uint32_t off = (uint32_t)(kk * APITCH + n4) * 2;
                sts2(sb + OFF_BHI + off, h01, h23);
                sts2(sb + OFF_BLO + off, l01, l23);
            }
        }

        // ---- gather A: 2 threads per row, 8 float4 each; hi/lo bf16 split ----
        {
            const int row = tid >> 1;
            const int j0  = (tid & 1) * 8;
            int gp = base + row;
            if (gp >= P) gp = P - 1;
            const int idx = __ldg(pin_k + gp);
            const float4* src = (const float4*)(feat + (size_t)idx * CCH) + j0;
            #pragma unroll
            for (int j = 0; j < 8; ++j) {
                float4 v = __ldg(src + j);
                uint32_t h01, l01, h23, l23;
                split2(v.x, v.y, h01, l01);
                split2(v.z, v.w, h23, l23);
                const uint32_t off = (uint32_t)(row * APITCH + (j0 + j) * 4) * 2;
                sts2(sb + OFF_AHI + off, h01, h23);
                sts2(sb + OFF_ALO + off, l01, l23);
            }
        }
        __syncthreads();

        // ---- 3-pass MMA: Ahi*Bhi + Ahi*Blo + Alo*Bhi, f32 accumulate ----
        float c[8][4];
        #pragma unroll
        for (int i = 0; i < 8; ++i)
            #pragma unroll
            for (int j = 0; j < 4; ++j) c[i][j] = 0.0f;

        #pragma unroll
        for (int pass = 0; pass < 3; ++pass) {
            const uint32_t aBase = sb + ((pass == 2) ? OFF_ALO : OFF_AHI) + aLaneOff;
            const uint32_t bBase = sb + ((pass == 1) ? OFF_BLO : OFF_BHI) + bLaneOff;
            #pragma unroll
            for (int ks = 0; ks < 4; ++ks) {
                uint32_t a[4];
                ldsm_x4(a[0], a[1], a[2], a[3], aBase + (uint32_t)(ks * 16) * 2);
                #pragma unroll
                for (int nb4 = 0; nb4 < 4; ++nb4) {
                    uint32_t b0, b1, b2, b3;
                    ldsm_x4_t(b0, b1, b2, b3,
                              bBase + (uint32_t)(ks * 16 * APITCH + nb4 * 16) * 2);
                    mma_bf16(c[nb4 * 2],     a, b0, b1);
                    mma_bf16(c[nb4 * 2 + 1], a, b2, b3);
                }
            }
        }

        // ---- epilogue: shfl-assemble 4 contiguous floats, red.global.add.v4 ----
        // lane tig pairs (e,e+1): even lane -> row gp0 cols [2e..2e+3],
        //                         odd  lane -> row gp1 cols [2e..2e+3]
        const int gp0 = base + warpM + groupID;
        const int gp1 = gp0 + 8;
        const bool odd = (tig & 1);
        const int gpm = odd ? gp1 : gp0;
        const bool valid = (gpm < P);
        const int o = valid ? __ldg(pout_k + gpm) : 0;
        float* rowp = out + (size_t)o * CCH + (tig >> 1) * 4;
        #pragma unroll
        for (int nb = 0; nb < 8; ++nb) {
            float e0 = __shfl_xor_sync(0xffffffffu, c[nb][0], 1);
            float e1 = __shfl_xor_sync(0xffffffffu, c[nb][1], 1);
            float e2 = __shfl_xor_sync(0xffffffffu, c[nb][2], 1);
            float e3 = __shfl_xor_sync(0xffffffffu, c[nb][3], 1);
            float v0 = odd ? e2 : c[nb][0];
            float v1 = odd ? e3 : c[nb][1];
            float v2 = odd ? c[nb][2] : e0;
            float v3 = odd ? c[nb][3] : e1;
            if (valid) red4(rowp + nb * 8, v0, v1, v2, v3);
        }
        __syncthreads();   // all warps done reading A/B before next overwrite
    }
}

// ---------------------------------------------------------------------------
__global__ void __launch_bounds__(256)
k_zero(float4* __restrict__ out4, int n4)
{
    int i = blockIdx.x * blockDim.x + threadIdx.x;
    const int s = gridDim.x * blockDim.x;
    const float4 z = make_float4(0.f, 0.f, 0.f, 0.f);
    for (; i < n4; i += s) out4[i] = z;
    if (blockIdx.x == 0 && threadIdx.x < 2 * CCH) g_stats[threadIdx.x] = 0.0f;
}

// ---------------------------------------------------------------------------
__global__ void __launch_bounds__(256)
k_stats(const float* __restrict__ out, int N)
{
    __shared__ float sh[256], sh2[256];
    const int tid = threadIdx.x;
    const int c = tid & 63;
    float s = 0.0f, s2 = 0.0f;
    for (int r = blockIdx.x * 4 + (tid >> 6); r < N; r += gridDim.x * 4) {
        float v = out[(size_t)r * CCH + c];
        s += v; s2 += v * v;
    }
    sh[tid] = s; sh2[tid] = s2;
    __syncthreads();
    if (tid < 64) {
        s  = sh[tid]  + sh[tid + 64]  + sh[tid + 128]  + sh[tid + 192];
        s2 = sh2[tid] + sh2[tid + 64] + sh2[tid + 128] + sh2[tid + 192];
        atomicAdd(&g_stats[tid], s);
        atomicAdd(&g_stats[64 + tid], s2);
    }
}

// ---------------------------------------------------------------------------
// Fused BN (batch stats; conv bias cancels exactly through training-mode BN)
// + ReLU, in place, float4-vectorized.
__global__ void __launch_bounds__(256)
k_norm(float* __restrict__ out, const float* __restrict__ gamma,
       const float* __restrict__ beta, int N)
{
    float4* o4 = (float4*)out;
    const int total4 = N * (CCH / 4);
    int i = blockIdx.x * blockDim.x + threadIdx.x;
    const int stride = gridDim.x * blockDim.x;   // multiple of 16 -> fixed channels
    if (i >= total4) return;

    const int cb = (i & 15) * 4;
    const float ninv = 1.0f / (float)N;
    float mean[4], scale[4], shift[4];
    #pragma unroll
    for (int j = 0; j < 4; ++j) {
        int c = cb + j;
        float m = g_stats[c] * ninv;
        float var = fmaxf(g_stats[64 + c] * ninv - m * m, 0.0f);
        mean[j] = m;
        scale[j] = rsqrtf(var + BN_EPS) * gamma[c];
        shift[j] = beta[c];
    }
    for (; i < total4; i += stride) {
        float4 v = o4[i];
        v.x = fmaxf((v.x - mean[0]) * scale[0] + shift[0], 0.0f);
        v.y = fmaxf((v.y - mean[1]) * scale[1] + shift[1], 0.0f);
        v.z = fmaxf((v.z - mean[2]) * scale[2] + shift[2], 0.0f);
        v.w = fmaxf((v.w - mean[3]) * scale[3] + shift[3], 0.0f);
        o4[i] = v;
    }
}

// ---------------------------------------------------------------------------
extern "C" void kernel_launch(void* const* d_in, const int* in_sizes, int n_in,
                              void* d_out, int out_size)
{
    const float* feat  = (const float*)d_in[0];   // [N_in, 64]
    const float* W     = (const float*)d_in[1];   // [K3, 64, 64]
    // d_in[2] = bias (cancels through training-mode BN)
    const float* gamma = (const float*)d_in[3];
    const float* beta  = (const float*)d_in[4];
    const int* pin  = (const int*)d_in[5];        // [K3, P]
    const int* pout = (const int*)d_in[6];        // [K3, P]

    const int K3 = in_sizes[1] / (CCH * CCH);
    const int P  = in_sizes[5] / K3;
    const int Nout = out_size / CCH;
    float* out = (float*)d_out;

    const int tilesPerK  = (P + MT - 1) / MT;
    const int tilesTotal = K3 * tilesPerK;

    static int smem_set = 0;
    if (!smem_set) {
        cudaFuncSetAttribute(k_scatter, cudaFuncAttributeMaxDynamicSharedMemorySize, SMEM_BYTES);
        smem_set = 1;
    }

    // 4 launches per call: (1) zero+stats-clear, (2) scatter-GEMM, (3) stats, (4) norm
    k_zero<<<1184, 256>>>((float4*)out, Nout * (CCH / 4));

    int grid = 296;                      // 2 persistent CTAs / SM
    if (grid > tilesTotal) grid = tilesTotal;
    k_scatter<<<grid, 256, SMEM_BYTES>>>(feat, W, pin, pout, out, P, tilesPerK, tilesTotal);

    int statsBlocks = (Nout + 3) / 4;
    if (statsBlocks > 1184) statsBlocks = 1184;
    k_stats<<<statsBlocks, 256>>>(out, Nout);

    int total4 = Nout * (CCH / 4);
    int normBlocks = (total4 + 255) / 256;
    if (normBlocks > 4096) normBlocks = 4096;
    k_norm<<<normBlocks, 256>>>(out, gamma, beta, Nout);
}

// round 17
// speedup vs baseline: 1.1419x; 1.1419x over previous
#include <cuda_runtime.h>
#include <cuda_fp16.h>
#include <cstdint>

#define CCH 64          // C_in == C_out == 64
#define MT  128         // pairs (M rows) per CTA tile
#define APITCH 72       // fp16 elems per smem row (144 B) -> ldmatrix conflict-free
#define BN_EPS 1e-5f

// smem byte offsets (dynamic smem, 1024-aligned base)
#define OFF_A   0
#define OFF_BHI (MT * APITCH * 2)                 // 18432
#define OFF_BLO (OFF_BHI + CCH * APITCH * 2)      // 27648
#define SMEM_BYTES (OFF_BLO + CCH * APITCH * 2)   // 36864

__device__ float g_stats[2 * CCH];   // [0..63]=sum, [64..127]=sum of squares

// ======================= PTX helpers =======================
static __device__ __forceinline__ uint32_t smem_u32(const void* p) {
    uint32_t a;
    asm("{ .reg .u64 t; cvta.to.shared.u64 t, %1; cvt.u32.u64 %0, t; }" : "=r"(a) : "l"(p));
    return a;
}
static __device__ __forceinline__ void ldsm_x4(uint32_t& r0, uint32_t& r1,
                                               uint32_t& r2, uint32_t& r3, uint32_t addr) {
    asm volatile("ldmatrix.sync.aligned.m8n8.x4.shared.b16 {%0,%1,%2,%3}, [%4];"
                 : "=r"(r0), "=r"(r1), "=r"(r2), "=r"(r3) : "r"(addr));
}
static __device__ __forceinline__ void ldsm_x4_t(uint32_t& r0, uint32_t& r1,
                                                 uint32_t& r2, uint32_t& r3, uint32_t addr) {
    asm volatile("ldmatrix.sync.aligned.m8n8.x4.trans.shared.b16 {%0,%1,%2,%3}, [%4];"
                 : "=r"(r0), "=r"(r1), "=r"(r2), "=r"(r3) : "r"(addr));
}
static __device__ __forceinline__ void mma_f16(float* c, const uint32_t* a,
                                               uint32_t b0, uint32_t b1) {
    asm volatile(
        "mma.sync.aligned.m16n8k16.row.col.f32.f16.f16.f32 "
        "{%0,%1,%2,%3}, {%4,%5,%6,%7}, {%8,%9}, {%0,%1,%2,%3};"
        : "+f"(c[0]), "+f"(c[1]), "+f"(c[2]), "+f"(c[3])
        : "r"(a[0]), "r"(a[1]), "r"(a[2]), "r"(a[3]), "r"(b0), "r"(b1));
}
static __device__ __forceinline__ void red4(float* p, float a, float b, float c, float d) {
    asm volatile("red.global.add.v4.f32 [%0], {%1,%2,%3,%4};"
                 :: "l"(p), "f"(a), "f"(b), "f"(c), "f"(d) : "memory");
}
static __device__ __forceinline__ void sts2(uint32_t addr, uint32_t a, uint32_t b) {
    asm volatile("st.shared.v2.b32 [%0], {%1,%2};" :: "r"(addr), "r"(a), "r"(b));
}
static __device__ __forceinline__ uint32_t h2pack(float x, float y) {
    __half2 h = __float22half2_rn(make_float2(x, y));
    return *reinterpret_cast<uint32_t*>(&h);
}
// f32 pair -> fp16 hi + fp16 lo (residual) packed u32 each
static __device__ __forceinline__ void h2split(float x, float y, uint32_t& hi, uint32_t& lo) {
    __half2 h = __float22half2_rn(make_float2(x, y));
    float2 hf = __half22float2(h);
    __half2 l = __float22half2_rn(make_float2(x - hf.x, y - hf.y));
    hi = *reinterpret_cast<uint32_t*>(&h);
    lo = *reinterpret_cast<uint32_t*>(&l);
}

// ===========================================================================
// Gather -> 128x64x64 GEMM: A fp16 single, B fp16 hi/lo (2 passes) -> scatter
// ===========================================================================
__global__ void __launch_bounds__(256, 2)
k_scatter(const float* __restrict__ feat, const float* __restrict__ W,
          const int* __restrict__ pin, const int* __restrict__ pout,
          float* __restrict__ out, int P, int tilesPerK)
{
    extern __shared__ __align__(1024) char smem[];
    const uint32_t sb = smem_u32(smem);

    const int tid  = threadIdx.x;
    const int warp = tid >> 5;
    const int lane = tid & 31;
    const int k    = blockIdx.x / tilesPerK;
    const int pb   = blockIdx.x - k * tilesPerK;
    const int base = pb * MT;
    const int* pin_k  = pin  + (size_t)k * P;
    const int* pout_k = pout + (size_t)k * P;

    // ---- weight tile: W[k]=[ci][co] row-major = B[k=ci][n=co]; fp16 hi/lo ----
    {
        const float4* Wv = (const float4*)(W + (size_t)k * CCH * CCH);
        #pragma unroll
        for (int t = tid; t < CCH * CCH / 4; t += 256) {
            const int kk = t >> 4, n4 = (t & 15) * 4;
            float4 v = __ldg(Wv + t);
            uint32_t h01, l01, h23, l23;
            h2split(v.x, v.y, h01, l01);
            h2split(v.z, v.w, h23, l23);
            const uint32_t off = (uint32_t)(kk * APITCH + n4) * 2;
            sts2(sb + OFF_BHI + off, h01, h23);
            sts2(sb + OFF_BLO + off, l01, l23);
        }
    }

    // ---- gather A: 2 threads per row, 8 float4 each; single fp16 round ----
    {
        const int row = tid >> 1;
        const int j0  = (tid & 1) * 8;
        int gp = base + row;
        if (gp >= P) gp = P - 1;
        const int idx = __ldg(pin_k + gp);
        const float4* src = (const float4*)(feat + (size_t)idx * CCH) + j0;
        #pragma unroll
        for (int j = 0; j < 8; ++j) {
            float4 v = __ldg(src + j);
            const uint32_t off = (uint32_t)(row * APITCH + (j0 + j) * 4) * 2;
            sts2(sb + OFF_A + off, h2pack(v.x, v.y), h2pack(v.z, v.w));
        }
    }
    __syncthreads();

    // ---- 2-pass MMA: A*Bhi + A*Blo, f32 accumulate, A frags reused ----
    float c[8][4];
    #pragma unroll
    for (int i = 0; i < 8; ++i)
        #pragma unroll
        for (int j = 0; j < 4; ++j) c[i][j] = 0.0f;

    const int warpM = warp * 16;
    const int lrow  = lane & 15;
    const int lhalf = (lane >> 4) * 8;
    const uint32_t aBase = sb + OFF_A + (uint32_t)((warpM + lrow) * APITCH + lhalf) * 2;
    const uint32_t bLaneOff = (uint32_t)(lrow * APITCH + lhalf) * 2;
    const uint32_t bHiBase = sb + OFF_BHI + bLaneOff;
    const uint32_t bLoBase = sb + OFF_BLO + bLaneOff;

    #pragma unroll
    for (int ks = 0; ks < 4; ++ks) {
        uint32_t a[4];
        ldsm_x4(a[0], a[1], a[2], a[3], aBase + (uint32_t)(ks * 16) * 2);
        const uint32_t kOff = (uint32_t)(ks * 16 * APITCH) * 2;
        #pragma unroll
        for (int nb4 = 0; nb4 < 4; ++nb4) {
            uint32_t b0, b1, b2, b3;
            ldsm_x4_t(b0, b1, b2, b3, bHiBase + kOff + (uint32_t)(nb4 * 16) * 2);
            mma_f16(c[nb4 * 2],     a, b0, b1);
            mma_f16(c[nb4 * 2 + 1], a, b2, b3);
        }
        #pragma unroll
        for (int nb4 = 0; nb4 < 4; ++nb4) {
            uint32_t b0, b1, b2, b3;
            ldsm_x4_t(b0, b1, b2, b3, bLoBase + kOff + (uint32_t)(nb4 * 16) * 2);
            mma_f16(c[nb4 * 2],     a, b0, b1);
            mma_f16(c[nb4 * 2 + 1], a, b2, b3);
        }
    }

    // ---- epilogue: shfl-assemble 4 contiguous floats, red.global.add.v4 ----
    const int groupID = lane >> 2;
    const int tig     = lane & 3;
    const int gp0 = base + warpM + groupID;
    const int gp1 = gp0 + 8;
    const bool odd = (tig & 1);
    const int gpm = odd ? gp1 : gp0;
    const bool valid = (gpm < P);
    const int o = valid ? __ldg(pout_k + gpm) : 0;
    float* rowp = out + (size_t)o * CCH + (tig >> 1) * 4;
    #pragma unroll
    for (int nb = 0; nb < 8; ++nb) {
        float e0 = __shfl_xor_sync(0xffffffffu, c[nb][0], 1);
        float e1 = __shfl_xor_sync(0xffffffffu, c[nb][1], 1);
        float e2 = __shfl_xor_sync(0xffffffffu, c[nb][2], 1);
        float e3 = __shfl_xor_sync(0xffffffffu, c[nb][3], 1);
        float v0 = odd ? e2 : c[nb][0];
        float v1 = odd ? e3 : c[nb][1];
        float v2 = odd ? c[nb][2] : e0;
        float v3 = odd ? c[nb][3] : e1;
        if (valid) red4(rowp + nb * 8, v0, v1, v2, v3);
    }
}

// ---------------------------------------------------------------------------
__global__ void __launch_bounds__(256)
k_zero(float4* __restrict__ out4, int n4)
{
    int i = blockIdx.x * blockDim.x + threadIdx.x;
    const int s = gridDim.x * blockDim.x;
    const float4 z = make_float4(0.f, 0.f, 0.f, 0.f);
    for (; i < n4; i += s) out4[i] = z;
    if (blockIdx.x == 0 && threadIdx.x < 2 * CCH) g_stats[threadIdx.x] = 0.0f;
}

// ---------------------------------------------------------------------------
__global__ void __launch_bounds__(256)
k_stats(const float* __restrict__ out, int N)
{
    __shared__ float sh[256], sh2[256];
    const int tid = threadIdx.x;
    const int c = tid & 63;
    float s = 0.0f, s2 = 0.0f;
    for (int r = blockIdx.x * 4 + (tid >> 6); r < N; r += gridDim.x * 4) {
        float v = out[(size_t)r * CCH + c];
        s += v; s2 += v * v;
    }
    sh[tid] = s; sh2[tid] = s2;
    __syncthreads();
    if (tid < 64) {
        s  = sh[tid]  + sh[tid + 64]  + sh[tid + 128]  + sh[tid + 192];
        s2 = sh2[tid] + sh2[tid + 64] + sh2[tid + 128] + sh2[tid + 192];
        atomicAdd(&g_stats[tid], s);
        atomicAdd(&g_stats[64 + tid], s2);
    }
}

// ---------------------------------------------------------------------------
// Fused BN (batch stats; conv bias cancels exactly through training-mode BN)
// + ReLU, in place, float4-vectorized.
__global__ void __launch_bounds__(256)
k_norm(float* __restrict__ out, const float* __restrict__ gamma,
       const float* __restrict__ beta, int N)
{
    float4* o4 = (float4*)out;
    const int total4 = N * (CCH / 4);
    int i = blockIdx.x * blockDim.x + threadIdx.x;
    const int stride = gridDim.x * blockDim.x;   // multiple of 16 -> fixed channels
    if (i >= total4) return;

    const int cb = (i & 15) * 4;
    const float ninv = 1.0f / (float)N;
    float mean[4], scale[4], shift[4];
    #pragma unroll
    for (int j = 0; j < 4; ++j) {
        int c = cb + j;
        float m = g_stats[c] * ninv;
        float var = fmaxf(g_stats[64 + c] * ninv - m * m, 0.0f);
        mean[j] = m;
        scale[j] = rsqrtf(var + BN_EPS) * gamma[c];
        shift[j] = beta[c];
    }
    for (; i < total4; i += stride) {
        float4 v = o4[i];
        v.x = fmaxf((v.x - mean[0]) * scale[0] + shift[0], 0.0f);
        v.y = fmaxf((v.y - mean[1]) * scale[1] + shift[1], 0.0f);
        v.z = fmaxf((v.z - mean[2]) * scale[2] + shift[2], 0.0f);
        v.w = fmaxf((v.w - mean[3]) * scale[3] + shift[3], 0.0f);
        o4[i] = v;
    }
}

// ---------------------------------------------------------------------------
extern "C" void kernel_launch(void* const* d_in, const int* in_sizes, int n_in,
                              void* d_out, int out_size)
{
    const float* feat  = (const float*)d_in[0];   // [N_in, 64]
    const float* W     = (const float*)d_in[1];   // [K3, 64, 64]
    // d_in[2] = bias (cancels through training-mode BN)
    const float* gamma = (const float*)d_in[3];
    const float* beta  = (const float*)d_in[4];
    const int* pin  = (const int*)d_in[5];        // [K3, P]
    const int* pout = (const int*)d_in[6];        // [K3, P]

    const int K3 = in_sizes[1] / (CCH * CCH);
    const int P  = in_sizes[5] / K3;
    const int Nout = out_size / CCH;
    float* out = (float*)d_out;

    const int tilesPerK = (P + MT - 1) / MT;

    static int smem_set = 0;
    if (!smem_set) {
        cudaFuncSetAttribute(k_scatter, cudaFuncAttributeMaxDynamicSharedMemorySize, SMEM_BYTES);
        smem_set = 1;
    }

    // 4 launches per call: (1) zero+stats-clear, (2) scatter-GEMM, (3) stats, (4) norm
    k_zero<<<1184, 256>>>((float4*)out, Nout * (CCH / 4));

    k_scatter<<<K3 * tilesPerK, 256, SMEM_BYTES>>>(feat, W, pin, pout, out, P, tilesPerK);

    int statsBlocks = (Nout + 3) / 4;
    if (statsBlocks > 1184) statsBlocks = 1184;
    k_stats<<<statsBlocks, 256>>>(out, Nout);

    int total4 = Nout * (CCH / 4);
    int normBlocks = (total4 + 255) / 256;
    if (normBlocks > 4096) normBlocks = 4096;
    k_norm<<<normBlocks, 256>>>(out, gamma, beta, Nout);
}